// round 16
// baseline (speedup 1.0000x reference)
#include <cuda_runtime.h>

#define NN 8192
#define FF 256
#define DD 64
#define KK 2
#define NWRD (NN/32)     /* 256 words per packed row */
#define TI 128           /* i-tile per CTA */
#define TJ 16            /* j-chunk (R16: halved for occupancy 3) */
#define NCH (NN/TJ)      /* 512 chunks */
#define JSPLIT 7

// dynamic smem layout for k_main
#define SM_WSD_BYTES (2*TJ*TI*8)            /* float2 wsd[2][16][128] = 32 KB */
#define SM_GS_OFF    SM_WSD_BYTES
#define SM_BYTES     (SM_WSD_BYTES + 2*TJ*DD*4)   /* + float Gs[2][1024] = 8 KB => 40 KB */

// -------- scratch (device globals; no allocation allowed) --------
__device__ float    g_HW  [KK*NN*DD];         // 4 MB   HW[k,n,d]
__device__ float    g_e1  [KK*NN];
__device__ float    g_e2  [KK*NN];
__device__ float    g_p2  [KK*NN];            // exp(e2)
__device__ float    g_q2  [KK*NN];            // exp(0.2 e2)
__device__ float    g_p1z [KK*NN];            // exp(e1)/Z
__device__ float    g_q1z [KK*NN];            // exp(0.2 e1)/Z
__device__ unsigned g_Apack[NN*NWRD];         // 8 MB   bit i of row j
__device__ float    g_part[JSPLIT*KK*NN*DD];  // 29 MB  j-split partials

#define FFMA2(c,a,b) asm("fma.rn.f32x2 %0, %1, %2, %0;" : "+l"(c) : "l"(a), "l"(b))

// ============================================================================
// K1: HW[k,n,d] = H @ W  plus e1/e2 head-vectors and exp tables p2/q2.
// ============================================================================
__global__ __launch_bounds__(256) void k_hw(const float* __restrict__ H,
                                            const float* __restrict__ Wt,
                                            const float* __restrict__ a1,
                                            const float* __restrict__ a2) {
    __shared__ float Hs[16][68];
    __shared__ float Ws[16][128];
    const int tid  = threadIdx.x;
    const int n0   = blockIdx.x * 64;
    const int lane = tid & 31;
    const int ngrp = tid >> 5;
    const int c_t  = lane * 4;
    const int n_t  = ngrp * 8;

    float acc[8][4];
    #pragma unroll
    for (int a = 0; a < 8; a++)
        #pragma unroll
        for (int c = 0; c < 4; c++) acc[a][c] = 0.f;

    for (int f0 = 0; f0 < FF; f0 += 16) {
        {
            int nn  = tid >> 2;
            int ffb = (tid & 3) * 4;
            float4 h4 = *(const float4*)&H[(n0+nn)*FF + f0 + ffb];
            Hs[ffb+0][nn] = h4.x; Hs[ffb+1][nn] = h4.y;
            Hs[ffb+2][nn] = h4.z; Hs[ffb+3][nn] = h4.w;
        }
        {
            int ff = tid >> 4;
            int c  = (tid & 15) * 8;
            int k  = c >> 6, d = c & 63;
            const float* wp = &Wt[(k*FF + f0 + ff)*DD + d];
            float4 w0 = *(const float4*)wp;
            float4 w1 = *(const float4*)(wp + 4);
            *(float4*)&Ws[ff][c]   = w0;
            *(float4*)&Ws[ff][c+4] = w1;
        }
        __syncthreads();
        #pragma unroll
        for (int ff = 0; ff < 16; ff++) {
            float4 wv = *(const float4*)&Ws[ff][c_t];
            float4 h0 = *(const float4*)&Hs[ff][n_t];
            float4 h1 = *(const float4*)&Hs[ff][n_t+4];
            float hv[8] = {h0.x,h0.y,h0.z,h0.w,h1.x,h1.y,h1.z,h1.w};
            #pragma unroll
            for (int nn2 = 0; nn2 < 8; nn2++) {
                acc[nn2][0] += hv[nn2]*wv.x;
                acc[nn2][1] += hv[nn2]*wv.y;
                acc[nn2][2] += hv[nn2]*wv.z;
                acc[nn2][3] += hv[nn2]*wv.w;
            }
        }
        __syncthreads();
    }

    const int k  = c_t >> 6;
    const int d0 = c_t & 63;
    float a1v[4], a2v[4];
    #pragma unroll
    for (int cc = 0; cc < 4; cc++) {
        a1v[cc] = a1[k*DD + d0 + cc];
        a2v[cc] = a2[k*DD + d0 + cc];
    }
    #pragma unroll
    for (int nn2 = 0; nn2 < 8; nn2++) {
        int n = n0 + n_t + nn2;
        *(float4*)&g_HW[(k*NN + n)*DD + d0] =
            make_float4(acc[nn2][0], acc[nn2][1], acc[nn2][2], acc[nn2][3]);
        float s1 = acc[nn2][0]*a1v[0] + acc[nn2][1]*a1v[1] + acc[nn2][2]*a1v[2] + acc[nn2][3]*a1v[3];
        float s2 = acc[nn2][0]*a2v[0] + acc[nn2][1]*a2v[1] + acc[nn2][2]*a2v[2] + acc[nn2][3]*a2v[3];
        #pragma unroll
        for (int off = 8; off > 0; off >>= 1) {
            s1 += __shfl_xor_sync(0xffffffffu, s1, off);
            s2 += __shfl_xor_sync(0xffffffffu, s2, off);
        }
        if ((lane & 15) == 0) {
            g_e1[k*NN + n] = s1;
            g_e2[k*NN + n] = s2;
            g_p2[k*NN + n] = __expf(s2);
            g_q2[k*NN + n] = __expf(0.2f*s2);
        }
    }
}

// ============================================================================
// K2: read A once (256 MB): pack to bitmask (byte-wise, int4 loads) AND
//     accumulate softmax denominators Z[k,j]; fold 1/Z into j-side exps.
// ============================================================================
__global__ __launch_bounds__(256) void k_packz(const int* __restrict__ A) {
    const int tid  = threadIdx.x;
    const int lane = tid & 31;
    const int j0   = blockIdx.x * 16;
    __shared__ float ne[2][16], sp1[2][16], sq1[2][16];
    if (tid < 32) {
        int k = tid >> 4, jj = tid & 15;
        float e = g_e1[k*NN + j0 + jj];
        ne [k][jj] = -e;
        sp1[k][jj] = __expf(e);
        sq1[k][jj] = __expf(0.2f*e);
    }
    __syncthreads();

    float z0[16], z1[16];
    #pragma unroll
    for (int jj = 0; jj < 16; jj++) { z0[jj] = 0.f; z1[jj] = 0.f; }

    unsigned char* Ab = (unsigned char*)g_Apack;

    for (int t = tid; t < NN/8; t += 256) {
        int i = t * 8;
        float e2v0[8], p2v0[8], q2v0[8], e2v1[8], p2v1[8], q2v1[8];
        #pragma unroll
        for (int p = 0; p < 8; p++) {
            e2v0[p] = g_e2[i+p];      p2v0[p] = g_p2[i+p];      q2v0[p] = g_q2[i+p];
            e2v1[p] = g_e2[NN+i+p];   p2v1[p] = g_p2[NN+i+p];   q2v1[p] = g_q2[NN+i+p];
        }
        #pragma unroll
        for (int jj = 0; jj < 16; jj++) {
            const int4* ap = (const int4*)&A[(size_t)(j0+jj)*NN + i];
            int4 a0 = ap[0];
            int4 a1i = ap[1];
            int av[8] = {a0.x,a0.y,a0.z,a0.w,a1i.x,a1i.y,a1i.z,a1i.w};
            unsigned byte = 0;
            #pragma unroll
            for (int p = 0; p < 8; p++) {
                if (av[p] != 0) {
                    byte |= (1u << p);
                    bool c0 = (e2v0[p] >= ne[0][jj]);
                    z0[jj] += (c0 ? sp1[0][jj] : sq1[0][jj]) * (c0 ? p2v0[p] : q2v0[p]);
                    bool c1 = (e2v1[p] >= ne[1][jj]);
                    z1[jj] += (c1 ? sp1[1][jj] : sq1[1][jj]) * (c1 ? p2v1[p] : q2v1[p]);
                }
            }
            Ab[(size_t)(j0+jj)*(NN/8) + t] = (unsigned char)byte;
        }
    }
    #pragma unroll
    for (int jj = 0; jj < 16; jj++) {
        #pragma unroll
        for (int off = 16; off > 0; off >>= 1) {
            z0[jj] += __shfl_xor_sync(0xffffffffu, z0[jj], off);
            z1[jj] += __shfl_xor_sync(0xffffffffu, z1[jj], off);
        }
    }
    __shared__ float zr[8][32];
    int w = tid >> 5;
    if (lane == 0) {
        #pragma unroll
        for (int jj = 0; jj < 16; jj++) { zr[w][jj*2] = z0[jj]; zr[w][jj*2+1] = z1[jj]; }
    }
    __syncthreads();
    if (tid < 32) {
        float s = 0.f;
        #pragma unroll
        for (int ww = 0; ww < 8; ww++) s += zr[ww][tid];
        int jj = tid >> 1, k = tid & 1;
        float e  = g_e1[k*NN + j0 + jj];
        float zi = 1.0f / s;
        g_p1z[k*NN + j0 + jj] = __expf(e)      * zi;
        g_q1z[k*NN + j0 + jj] = __expf(0.2f*e) * zi;
    }
}

// ============================================================================
// K3: main implicit matmul, software-pipelined (R12/R15 structure, TJ=16):
//     one __syncthreads per 16-j chunk; w-gen(c+1) + G-stage(c+1) interleave
//     with the FMA loop of chunk c (double-buffered dynamic smem, occ 3).
// ============================================================================
__global__ __launch_bounds__(128, 3) void k_main() {
    extern __shared__ char sm[];
    float2* wsd = (float2*)sm;                      // [2][TJ][TI]
    float*  Gs  = (float*)(sm + SM_GS_OFF);         // [2][TJ*DD]

    const int tid = threadIdx.x;
    const int i0  = blockIdx.x * TI;
    const int k   = blockIdx.y;
    const int js  = blockIdx.z;

    const int lane = tid & 31;
    const int wz   = tid >> 5;
    const int dg   = lane & 7;
    const int ig   = wz*4 + (lane >> 3);
    const int i_t  = ig * 8;
    const int dA   = dg * 4;
    const int dB   = 32 + dg * 4;

    const int   ii    = tid;
    const float e2i   = g_e2[k*NN + i0 + ii];
    const float p2i   = g_p2[k*NN + i0 + ii];
    const float q2i   = g_q2[k*NN + i0 + ii];
    const int   wword = ii >> 5;
    const int   bpos  = ii & 31;
    const int   apc   = i0 >> 5;

    unsigned long long acc[8][4];
    #pragma unroll
    for (int r = 0; r < 8; r++)
        #pragma unroll
        for (int q = 0; q < 4; q++) acc[r][q] = 0ull;

    const int c_beg = (js * NCH) / JSPLIT;
    const int c_end = ((js + 1) * NCH) / JSPLIT;
    const float* HWb = g_HW + (size_t)k*NN*DD;
    const float* e1b = g_e1 + k*NN;
    const float* p1b = g_p1z + k*NN;
    const float* q1b = g_q1z + k*NN;

    // --- generate chunk c into buffer p: G-stage + w-gen with float4 params ---
    #define GEN_CHUNK(c_, p_)                                                        \
    {                                                                                \
        const int jc_ = (c_) * TJ;                                                   \
        const float4* src_ = (const float4*)(HWb + (size_t)jc_*DD);                  \
        float4* dst_ = (float4*)(Gs + (p_)*(TJ*DD));                                 \
        dst_[tid]       = src_[tid];                                                 \
        dst_[tid + 128] = src_[tid + 128];                                           \
        float2* wb_ = wsd + (p_)*(TJ*TI);                                            \
        _Pragma("unroll")                                                            \
        for (int g4 = 0; g4 < TJ/4; g4++) {                                          \
            float4 e1v = __ldg((const float4*)(e1b + jc_ + g4*4));                   \
            float4 pzv = __ldg((const float4*)(p1b + jc_ + g4*4));                   \
            float4 qzv = __ldg((const float4*)(q1b + jc_ + g4*4));                   \
            float e1a[4] = {e1v.x, e1v.y, e1v.z, e1v.w};                             \
            float pza[4] = {pzv.x, pzv.y, pzv.z, pzv.w};                             \
            float qza[4] = {qzv.x, qzv.y, qzv.z, qzv.w};                             \
            _Pragma("unroll")                                                        \
            for (int u = 0; u < 4; u++) {                                            \
                const int jj = g4*4 + u;                                             \
                unsigned word = __ldg(&g_Apack[(size_t)(jc_ + jj)*NWRD + apc + wword]); \
                bool on   = (word >> bpos) & 1u;                                     \
                bool cnd  = (e2i >= -e1a[u]);                                        \
                float v = 0.f;                                                       \
                if (on) v = (cnd ? pza[u] : qza[u]) * (cnd ? p2i : q2i);             \
                wb_[jj*TI + ii] = make_float2(v, v);                                 \
            }                                                                        \
        }                                                                            \
    }

    GEN_CHUNK(c_beg, 0);
    __syncthreads();

    for (int c = c_beg; c < c_end; c++) {
        const int p = (c - c_beg) & 1;
        // prefetch/generate next chunk into the other buffer (overlaps with FMA below)
        if (c + 1 < c_end) GEN_CHUNK(c + 1, p ^ 1);

        const float2* wbase = wsd + p*(TJ*TI);
        const float*  gbase = Gs  + p*(TJ*DD);
        #pragma unroll 4
        for (int jj = 0; jj < TJ; jj++) {
            const ulonglong2* wp = (const ulonglong2*)&wbase[jj*TI + i_t];
            ulonglong2 w0 = wp[0], w1 = wp[1], w2 = wp[2], w3 = wp[3];
            const float* grow = &gbase[jj*DD];
            ulonglong2 ga = *(const ulonglong2*)(grow + dA);
            ulonglong2 gb = *(const ulonglong2*)(grow + dB);
            unsigned long long wv[8] = {w0.x,w0.y,w1.x,w1.y,w2.x,w2.y,w3.x,w3.y};
            #pragma unroll
            for (int r = 0; r < 8; r++) {
                FFMA2(acc[r][0], wv[r], ga.x);
                FFMA2(acc[r][1], wv[r], ga.y);
                FFMA2(acc[r][2], wv[r], gb.x);
                FFMA2(acc[r][3], wv[r], gb.y);
            }
        }
        __syncthreads();
    }

    float* part = g_part + (size_t)(js*KK + k)*NN*DD;
    #pragma unroll
    for (int r = 0; r < 8; r++) {
        union { unsigned long long u; float2 f; } a0, a1u, a2u, a3u;
        a0.u  = acc[r][0]; a1u.u = acc[r][1];
        a2u.u = acc[r][2]; a3u.u = acc[r][3];
        const int i = i0 + i_t + r;
        *(float4*)&part[(size_t)i*DD + dA] = make_float4(a0.f.x,  a0.f.y,  a1u.f.x, a1u.f.y);
        *(float4*)&part[(size_t)i*DD + dB] = make_float4(a2u.f.x, a2u.f.y, a3u.f.x, a3u.f.y);
    }
}

// ============================================================================
// K4: combine j-split partials + bias + ReLU -> out[n, k*64+d]
// ============================================================================
__global__ void k_epi(const float* __restrict__ b, float* __restrict__ out) {
    int idx = blockIdx.x*256 + threadIdx.x;     // N*128 total
    int n = idx >> 7, c = idx & 127;
    int k = c >> 6,  d = c & 63;
    size_t base = ((size_t)k*NN + n)*DD + d;
    const size_t S = (size_t)KK*NN*DD;
    float v = b[c];
    #pragma unroll
    for (int s = 0; s < JSPLIT; s++) v += g_part[base + (size_t)s*S];
    out[idx] = fmaxf(v, 0.f);
}

// ============================================================================
extern "C" void kernel_launch(void* const* d_in, const int* in_sizes, int n_in,
                              void* d_out, int out_size) {
    const float* H  = (const float*)d_in[0];
    const int*   A  = (const int*)  d_in[1];
    const float* W  = (const float*)d_in[2];
    const float* b  = (const float*)d_in[3];
    const float* a1 = (const float*)d_in[4];
    const float* a2 = (const float*)d_in[5];
    float* out = (float*)d_out;
    (void)in_sizes; (void)n_in; (void)out_size;

    // host-side attribute set: runs at capture time only; replays skip host code
    cudaFuncSetAttribute(k_main, cudaFuncAttributeMaxDynamicSharedMemorySize, SM_BYTES);

    k_hw   <<<128, 256>>>(H, W, a1, a2);
    k_packz<<<512, 256>>>(A);
    k_main <<<dim3(64, 2, JSPLIT), 128, SM_BYTES>>>();
    k_epi  <<<4096, 256>>>(b, out);
}

// round 17
// speedup vs baseline: 1.0911x; 1.0911x over previous
#include <cuda_runtime.h>

#define NN 8192
#define FF 256
#define DD 64
#define KK 2
#define NWRD (NN/32)     /* 256 words per packed row */
#define TI 128           /* i-tile per CTA */
#define TJ 32            /* j-chunk */
#define NCH (NN/TJ)      /* 256 chunks */
#define JSPLIT 7

// dynamic smem layout for k_main (w de-duplicated: float, not float2)
#define SM_WSD_BYTES (2*TJ*TI*4)            /* float wsd[2][32][128] = 32 KB */
#define SM_GS_OFF    SM_WSD_BYTES
#define SM_BYTES     (SM_WSD_BYTES + 2*TJ*DD*4)   /* + float Gs[2][2048] = 16 KB => 48 KB */

// -------- scratch (device globals; no allocation allowed) --------
__device__ float    g_HW  [KK*NN*DD];         // 4 MB   HW[k,n,d]
__device__ float    g_e1  [KK*NN];
__device__ float    g_e2  [KK*NN];
__device__ float    g_p2  [KK*NN];            // exp(e2)
__device__ float    g_q2  [KK*NN];            // exp(0.2 e2)
__device__ float    g_p1z [KK*NN];            // exp(e1)/Z
__device__ float    g_q1z [KK*NN];            // exp(0.2 e1)/Z
__device__ unsigned g_Apack[NN*NWRD];         // 8 MB   bit i of row j
__device__ float    g_part[JSPLIT*KK*NN*DD];  // 29 MB  j-split partials

#define FFMA2(c,a,b) asm("fma.rn.f32x2 %0, %1, %2, %0;" : "+l"(c) : "l"(a), "l"(b))
#define PACK2(out,w) asm("mov.b64 %0, {%1, %1};" : "=l"(out) : "f"(w))

// ============================================================================
// K1: HW[k,n,d] = H @ W  plus e1/e2 head-vectors and exp tables p2/q2.
// ============================================================================
__global__ __launch_bounds__(256) void k_hw(const float* __restrict__ H,
                                            const float* __restrict__ Wt,
                                            const float* __restrict__ a1,
                                            const float* __restrict__ a2) {
    __shared__ float Hs[16][68];
    __shared__ float Ws[16][128];
    const int tid  = threadIdx.x;
    const int n0   = blockIdx.x * 64;
    const int lane = tid & 31;
    const int ngrp = tid >> 5;
    const int c_t  = lane * 4;
    const int n_t  = ngrp * 8;

    float acc[8][4];
    #pragma unroll
    for (int a = 0; a < 8; a++)
        #pragma unroll
        for (int c = 0; c < 4; c++) acc[a][c] = 0.f;

    for (int f0 = 0; f0 < FF; f0 += 16) {
        {
            int nn  = tid >> 2;
            int ffb = (tid & 3) * 4;
            float4 h4 = *(const float4*)&H[(n0+nn)*FF + f0 + ffb];
            Hs[ffb+0][nn] = h4.x; Hs[ffb+1][nn] = h4.y;
            Hs[ffb+2][nn] = h4.z; Hs[ffb+3][nn] = h4.w;
        }
        {
            int ff = tid >> 4;
            int c  = (tid & 15) * 8;
            int k  = c >> 6, d = c & 63;
            const float* wp = &Wt[(k*FF + f0 + ff)*DD + d];
            float4 w0 = *(const float4*)wp;
            float4 w1 = *(const float4*)(wp + 4);
            *(float4*)&Ws[ff][c]   = w0;
            *(float4*)&Ws[ff][c+4] = w1;
        }
        __syncthreads();
        #pragma unroll
        for (int ff = 0; ff < 16; ff++) {
            float4 wv = *(const float4*)&Ws[ff][c_t];
            float4 h0 = *(const float4*)&Hs[ff][n_t];
            float4 h1 = *(const float4*)&Hs[ff][n_t+4];
            float hv[8] = {h0.x,h0.y,h0.z,h0.w,h1.x,h1.y,h1.z,h1.w};
            #pragma unroll
            for (int nn2 = 0; nn2 < 8; nn2++) {
                acc[nn2][0] += hv[nn2]*wv.x;
                acc[nn2][1] += hv[nn2]*wv.y;
                acc[nn2][2] += hv[nn2]*wv.z;
                acc[nn2][3] += hv[nn2]*wv.w;
            }
        }
        __syncthreads();
    }

    const int k  = c_t >> 6;
    const int d0 = c_t & 63;
    float a1v[4], a2v[4];
    #pragma unroll
    for (int cc = 0; cc < 4; cc++) {
        a1v[cc] = a1[k*DD + d0 + cc];
        a2v[cc] = a2[k*DD + d0 + cc];
    }
    #pragma unroll
    for (int nn2 = 0; nn2 < 8; nn2++) {
        int n = n0 + n_t + nn2;
        *(float4*)&g_HW[(k*NN + n)*DD + d0] =
            make_float4(acc[nn2][0], acc[nn2][1], acc[nn2][2], acc[nn2][3]);
        float s1 = acc[nn2][0]*a1v[0] + acc[nn2][1]*a1v[1] + acc[nn2][2]*a1v[2] + acc[nn2][3]*a1v[3];
        float s2 = acc[nn2][0]*a2v[0] + acc[nn2][1]*a2v[1] + acc[nn2][2]*a2v[2] + acc[nn2][3]*a2v[3];
        #pragma unroll
        for (int off = 8; off > 0; off >>= 1) {
            s1 += __shfl_xor_sync(0xffffffffu, s1, off);
            s2 += __shfl_xor_sync(0xffffffffu, s2, off);
        }
        if ((lane & 15) == 0) {
            g_e1[k*NN + n] = s1;
            g_e2[k*NN + n] = s2;
            g_p2[k*NN + n] = __expf(s2);
            g_q2[k*NN + n] = __expf(0.2f*s2);
        }
    }
}

// ============================================================================
// K2: read A once (256 MB): pack to bitmask (byte-wise, int4 loads) AND
//     accumulate softmax denominators Z[k,j]; fold 1/Z into j-side exps.
// ============================================================================
__global__ __launch_bounds__(256) void k_packz(const int* __restrict__ A) {
    const int tid  = threadIdx.x;
    const int lane = tid & 31;
    const int j0   = blockIdx.x * 16;
    __shared__ float ne[2][16], sp1[2][16], sq1[2][16];
    if (tid < 32) {
        int k = tid >> 4, jj = tid & 15;
        float e = g_e1[k*NN + j0 + jj];
        ne [k][jj] = -e;
        sp1[k][jj] = __expf(e);
        sq1[k][jj] = __expf(0.2f*e);
    }
    __syncthreads();

    float z0[16], z1[16];
    #pragma unroll
    for (int jj = 0; jj < 16; jj++) { z0[jj] = 0.f; z1[jj] = 0.f; }

    unsigned char* Ab = (unsigned char*)g_Apack;

    for (int t = tid; t < NN/8; t += 256) {
        int i = t * 8;
        float e2v0[8], p2v0[8], q2v0[8], e2v1[8], p2v1[8], q2v1[8];
        #pragma unroll
        for (int p = 0; p < 8; p++) {
            e2v0[p] = g_e2[i+p];      p2v0[p] = g_p2[i+p];      q2v0[p] = g_q2[i+p];
            e2v1[p] = g_e2[NN+i+p];   p2v1[p] = g_p2[NN+i+p];   q2v1[p] = g_q2[NN+i+p];
        }
        #pragma unroll
        for (int jj = 0; jj < 16; jj++) {
            const int4* ap = (const int4*)&A[(size_t)(j0+jj)*NN + i];
            int4 a0 = ap[0];
            int4 a1i = ap[1];
            int av[8] = {a0.x,a0.y,a0.z,a0.w,a1i.x,a1i.y,a1i.z,a1i.w};
            unsigned byte = 0;
            #pragma unroll
            for (int p = 0; p < 8; p++) {
                if (av[p] != 0) {
                    byte |= (1u << p);
                    bool c0 = (e2v0[p] >= ne[0][jj]);
                    z0[jj] += (c0 ? sp1[0][jj] : sq1[0][jj]) * (c0 ? p2v0[p] : q2v0[p]);
                    bool c1 = (e2v1[p] >= ne[1][jj]);
                    z1[jj] += (c1 ? sp1[1][jj] : sq1[1][jj]) * (c1 ? p2v1[p] : q2v1[p]);
                }
            }
            Ab[(size_t)(j0+jj)*(NN/8) + t] = (unsigned char)byte;
        }
    }
    #pragma unroll
    for (int jj = 0; jj < 16; jj++) {
        #pragma unroll
        for (int off = 16; off > 0; off >>= 1) {
            z0[jj] += __shfl_xor_sync(0xffffffffu, z0[jj], off);
            z1[jj] += __shfl_xor_sync(0xffffffffu, z1[jj], off);
        }
    }
    __shared__ float zr[8][32];
    int w = tid >> 5;
    if (lane == 0) {
        #pragma unroll
        for (int jj = 0; jj < 16; jj++) { zr[w][jj*2] = z0[jj]; zr[w][jj*2+1] = z1[jj]; }
    }
    __syncthreads();
    if (tid < 32) {
        float s = 0.f;
        #pragma unroll
        for (int ww = 0; ww < 8; ww++) s += zr[ww][tid];
        int jj = tid >> 1, k = tid & 1;
        float e  = g_e1[k*NN + j0 + jj];
        float zi = 1.0f / s;
        g_p1z[k*NN + j0 + jj] = __expf(e)      * zi;
        g_q1z[k*NN + j0 + jj] = __expf(0.2f*e) * zi;
    }
}

// ============================================================================
// K3: main implicit matmul, software-pipelined (R15 structure, TJ=32):
//     w stored ONCE (float), loaded as 2 conflict-free LDS.128 per jj and
//     packed to {w,w} in registers (mov.b64). 48 KB smem -> occupancy 3.
// ============================================================================
__global__ __launch_bounds__(128, 3) void k_main() {
    extern __shared__ char sm[];
    float* wsd = (float*)sm;                        // [2][TJ][TI]
    float* Gs  = (float*)(sm + SM_GS_OFF);          // [2][TJ*DD]

    const int tid = threadIdx.x;
    const int i0  = blockIdx.x * TI;
    const int k   = blockIdx.y;
    const int js  = blockIdx.z;

    const int lane = tid & 31;
    const int wz   = tid >> 5;
    const int dg   = lane & 7;
    const int ig   = wz*4 + (lane >> 3);
    const int i_t  = ig * 8;
    const int dA   = dg * 4;
    const int dB   = 32 + dg * 4;

    const int   ii    = tid;
    const float e2i   = g_e2[k*NN + i0 + ii];
    const float p2i   = g_p2[k*NN + i0 + ii];
    const float q2i   = g_q2[k*NN + i0 + ii];
    const int   wword = ii >> 5;
    const int   bpos  = ii & 31;
    const int   apc   = i0 >> 5;

    unsigned long long acc[8][4];
    #pragma unroll
    for (int r = 0; r < 8; r++)
        #pragma unroll
        for (int q = 0; q < 4; q++) acc[r][q] = 0ull;

    const int c_beg = (js * NCH) / JSPLIT;
    const int c_end = ((js + 1) * NCH) / JSPLIT;
    const float* HWb = g_HW + (size_t)k*NN*DD;
    const float* e1b = g_e1 + k*NN;
    const float* p1b = g_p1z + k*NN;
    const float* q1b = g_q1z + k*NN;

    // --- generate chunk c into buffer p: G-stage + w-gen (float4 params) ---
    #define GEN_CHUNK(c_, p_)                                                        \
    {                                                                                \
        const int jc_ = (c_) * TJ;                                                   \
        const float4* src_ = (const float4*)(HWb + (size_t)jc_*DD);                  \
        float4* dst_ = (float4*)(Gs + (p_)*(TJ*DD));                                 \
        dst_[tid]       = src_[tid];                                                 \
        dst_[tid + 128] = src_[tid + 128];                                           \
        dst_[tid + 256] = src_[tid + 256];                                           \
        dst_[tid + 384] = src_[tid + 384];                                           \
        float* wb_ = wsd + (p_)*(TJ*TI);                                             \
        _Pragma("unroll")                                                            \
        for (int g4 = 0; g4 < TJ/4; g4++) {                                          \
            float4 e1v = __ldg((const float4*)(e1b + jc_ + g4*4));                   \
            float4 pzv = __ldg((const float4*)(p1b + jc_ + g4*4));                   \
            float4 qzv = __ldg((const float4*)(q1b + jc_ + g4*4));                   \
            float e1a[4] = {e1v.x, e1v.y, e1v.z, e1v.w};                             \
            float pza[4] = {pzv.x, pzv.y, pzv.z, pzv.w};                             \
            float qza[4] = {qzv.x, qzv.y, qzv.z, qzv.w};                             \
            _Pragma("unroll")                                                        \
            for (int u = 0; u < 4; u++) {                                            \
                const int jj = g4*4 + u;                                             \
                unsigned word = __ldg(&g_Apack[(size_t)(jc_ + jj)*NWRD + apc + wword]); \
                bool on   = (word >> bpos) & 1u;                                     \
                bool cnd  = (e2i >= -e1a[u]);                                        \
                float v = 0.f;                                                       \
                if (on) v = (cnd ? pza[u] : qza[u]) * (cnd ? p2i : q2i);             \
                wb_[jj*TI + ii] = v;                                                 \
            }                                                                        \
        }                                                                            \
    }

    GEN_CHUNK(c_beg, 0);
    __syncthreads();

    for (int c = c_beg; c < c_end; c++) {
        const int p = (c - c_beg) & 1;
        // prefetch/generate next chunk into the other buffer (overlaps with FMA below)
        if (c + 1 < c_end) GEN_CHUNK(c + 1, p ^ 1);

        const float* wbase = wsd + p*(TJ*TI);
        const float* gbase = Gs  + p*(TJ*DD);
        #pragma unroll 4
        for (int jj = 0; jj < TJ; jj++) {
            const float4* wp = (const float4*)&wbase[jj*TI + i_t];
            float4 wa = wp[0], wb = wp[1];      // 8 w's, conflict-free LDS.128 pair
            const float* grow = &gbase[jj*DD];
            ulonglong2 ga = *(const ulonglong2*)(grow + dA);
            ulonglong2 gb = *(const ulonglong2*)(grow + dB);
            float wf[8] = {wa.x, wa.y, wa.z, wa.w, wb.x, wb.y, wb.z, wb.w};
            unsigned long long wv[8];
            #pragma unroll
            for (int r = 0; r < 8; r++) PACK2(wv[r], wf[r]);
            #pragma unroll
            for (int r = 0; r < 8; r++) {
                FFMA2(acc[r][0], wv[r], ga.x);
                FFMA2(acc[r][1], wv[r], ga.y);
                FFMA2(acc[r][2], wv[r], gb.x);
                FFMA2(acc[r][3], wv[r], gb.y);
            }
        }
        __syncthreads();
    }

    float* part = g_part + (size_t)(js*KK + k)*NN*DD;
    #pragma unroll
    for (int r = 0; r < 8; r++) {
        union { unsigned long long u; float2 f; } a0, a1u, a2u, a3u;
        a0.u  = acc[r][0]; a1u.u = acc[r][1];
        a2u.u = acc[r][2]; a3u.u = acc[r][3];
        const int i = i0 + i_t + r;
        *(float4*)&part[(size_t)i*DD + dA] = make_float4(a0.f.x,  a0.f.y,  a1u.f.x, a1u.f.y);
        *(float4*)&part[(size_t)i*DD + dB] = make_float4(a2u.f.x, a2u.f.y, a3u.f.x, a3u.f.y);
    }
}

// ============================================================================
// K4: combine j-split partials + bias + ReLU -> out[n, k*64+d]
// ============================================================================
__global__ void k_epi(const float* __restrict__ b, float* __restrict__ out) {
    int idx = blockIdx.x*256 + threadIdx.x;     // N*128 total
    int n = idx >> 7, c = idx & 127;
    int k = c >> 6,  d = c & 63;
    size_t base = ((size_t)k*NN + n)*DD + d;
    const size_t S = (size_t)KK*NN*DD;
    float v = b[c];
    #pragma unroll
    for (int s = 0; s < JSPLIT; s++) v += g_part[base + (size_t)s*S];
    out[idx] = fmaxf(v, 0.f);
}

// ============================================================================
extern "C" void kernel_launch(void* const* d_in, const int* in_sizes, int n_in,
                              void* d_out, int out_size) {
    const float* H  = (const float*)d_in[0];
    const int*   A  = (const int*)  d_in[1];
    const float* W  = (const float*)d_in[2];
    const float* b  = (const float*)d_in[3];
    const float* a1 = (const float*)d_in[4];
    const float* a2 = (const float*)d_in[5];
    float* out = (float*)d_out;
    (void)in_sizes; (void)n_in; (void)out_size;

    // host-side attribute set: runs at capture time only; replays skip host code
    cudaFuncSetAttribute(k_main, cudaFuncAttributeMaxDynamicSharedMemorySize, SM_BYTES);

    k_hw   <<<128, 256>>>(H, W, a1, a2);
    k_packz<<<512, 256>>>(A);
    k_main <<<dim3(64, 2, JSPLIT), 128, SM_BYTES>>>();
    k_epi  <<<4096, 256>>>(b, out);
}